// round 4
// baseline (speedup 1.0000x reference)
#include <cuda_runtime.h>
#include <cuda_bf16.h>

// Problem constants: B=16384, T=60, I=32, H=128, SEQLEN=30 -> 30 decode steps.
// Reference is autoregressive: x_{t+1} = y_t; only x[:,30,:] is consumed.

#define BATCH   16384
#define TT      60
#define II      32
#define HH      128
#define STEPS   30
#define TM      32          // batch rows per CTA
#define NCTA    (BATCH / TM)   // 512
#define NTHR    256

// ---- device scratch (transposed weights), static allocation (allowed) ----
__device__ float g_WhhT[HH * 3 * HH];   // [k=128][j=384]
__device__ float g_WihT[II * 3 * HH];   // [k=32][j=384]
__device__ float g_WoutT[HH * II];      // [c=128][i=32]

__global__ void prep_kernel(const float* __restrict__ Wih,
                            const float* __restrict__ Whh,
                            const float* __restrict__ Wout) {
    int i = blockIdx.x * blockDim.x + threadIdx.x;
    if (i < 3 * HH * HH) {          // W_hh: (384,128) -> T[k][j]
        int j = i / HH, k = i % HH;
        g_WhhT[k * (3 * HH) + j] = Whh[i];
    }
    if (i < 3 * HH * II) {          // W_ih: (384,32) -> T[k][j]
        int j = i / II, k = i % II;
        g_WihT[k * (3 * HH) + j] = Wih[i];
    }
    if (i < II * HH) {              // W_out: (32,128) -> T[c][i]
        int r = i / HH, c = i % HH;
        g_WoutT[c * II + r] = Wout[i];
    }
}

// smem: W_hhT (128*384) + h tile (32*128) + x tile (32*32)
#define SM_WT_F  (HH * 3 * HH)          // 49152 floats
#define SM_H_F   (TM * HH)              // 4096
#define SM_X_F   (TM * II)              // 1024
#define SMEM_BYTES ((SM_WT_F + SM_H_F + SM_X_F) * 4)   // 217088 B

__device__ __forceinline__ float4 ld4(const float* p) { return *(const float4*)p; }
__device__ __forceinline__ float4 add4(float4 a, float4 b) {
    return make_float4(a.x + b.x, a.y + b.y, a.z + b.z, a.w + b.w);
}
__device__ __forceinline__ void fma4(float4& acc, float s, float4 w) {
    acc.x = fmaf(s, w.x, acc.x);
    acc.y = fmaf(s, w.y, acc.y);
    acc.z = fmaf(s, w.z, acc.z);
    acc.w = fmaf(s, w.w, acc.w);
}

__device__ __forceinline__ float sigmoidf_fast(float v) {
    float e = __expf(-v);                 // v>>0: e->0 -> 1 ; v<<0: e->inf -> 0
    return __fdividef(1.0f, 1.0f + e);
}
__device__ __forceinline__ float tanhf_fast(float a) {
    float e2 = __expf(2.0f * a);          // inf-safe: 1 - 2/inf = 1 ; 1 - 2/1 = -1
    return 1.0f - __fdividef(2.0f, e2 + 1.0f);
}
__device__ __forceinline__ float gru_gate(float rp, float zp, float inp, float hnp, float hold) {
    float r = sigmoidf_fast(rp);
    float z = sigmoidf_fast(zp);
    float n = tanhf_fast(fmaf(r, hnp, inp));
    return fmaf(z, hold - n, n);          // (1-z)*n + z*h
}

__global__ __launch_bounds__(NTHR, 1)
void gru_kernel(const float* __restrict__ x,
                const float* __restrict__ h0,
                const float* __restrict__ b_ih,
                const float* __restrict__ b_hh,
                const float* __restrict__ b_out,
                float* __restrict__ out) {
    extern __shared__ float sm[];
    float* sWT = sm;                       // [128][384]
    float* sH  = sm + SM_WT_F;             // [32][128]
    float* sX  = sH + SM_H_F;              // [32][32]

    const int tid = threadIdx.x;
    const int rowBase = blockIdx.x * TM;

    // ---- stage weights / state into smem (all coalesced float4) ----
    {
        const float4* src = (const float4*)g_WhhT;
        float4* dst = (float4*)sWT;
        #pragma unroll 4
        for (int i = tid; i < SM_WT_F / 4; i += NTHR) dst[i] = src[i];
    }
    {
        const float4* src = (const float4*)(h0 + (size_t)rowBase * HH);
        float4* dst = (float4*)sH;
        for (int i = tid; i < SM_H_F / 4; i += NTHR) dst[i] = src[i];
    }
    {   // x0 = x[:, 30, :]  (row stride 60*32=1920 floats, offset 960)
        const float4* xv = (const float4*)x;
        float4* dst = (float4*)sX;
        int r = tid >> 3, q = tid & 7;     // 32 rows * 8 float4 = 256 threads
        dst[tid] = xv[(size_t)(rowBase + r) * (TT * II / 4) + (960 / 4) + q];
    }

    // thread tile mapping: warp cm handles rows m0..m0+3, lane cc handles cols c0..c0+3
    const int cm = tid >> 5, cc = tid & 31;
    const int m0 = cm * 4, c0 = cc * 4;
    const int lane = cc;

    // per-thread bias preload (constant across steps)
    const float4 br  = add4(ld4(b_ih + c0),        ld4(b_hh + c0));
    const float4 bz  = add4(ld4(b_ih + HH + c0),   ld4(b_hh + HH + c0));
    const float4 bin = ld4(b_ih + 2 * HH + c0);
    const float4 bhn = ld4(b_hh + 2 * HH + c0);
    const float  by  = b_out[lane];

    __syncthreads();

    for (int t = 0; t < STEPS; t++) {
        float4 ar[4], az[4], ahn[4], ain[4];
        #pragma unroll
        for (int d = 0; d < 4; d++) { ar[d] = br; az[d] = bz; ahn[d] = bhn; ain[d] = bin; }

        // ---- gh accumulation: K=128 over smem W_hhT ----
        #pragma unroll 4
        for (int k = 0; k < HH; k++) {
            const float* wrow = sWT + k * (3 * HH);
            float4 wr = ld4(wrow + c0);
            float4 wz = ld4(wrow + HH + c0);
            float4 wn = ld4(wrow + 2 * HH + c0);
            #pragma unroll
            for (int d = 0; d < 4; d++) {
                float hs = sH[(m0 + d) * HH + k];     // warp broadcast
                fma4(ar[d],  hs, wr);
                fma4(az[d],  hs, wz);
                fma4(ahn[d], hs, wn);
            }
        }

        // ---- gi accumulation: K=32 over L2-resident W_ihT ----
        #pragma unroll 4
        for (int k = 0; k < II; k++) {
            const float* wrow = g_WihT + k * (3 * HH);
            float4 wr = ld4(wrow + c0);
            float4 wz = ld4(wrow + HH + c0);
            float4 wn = ld4(wrow + 2 * HH + c0);
            #pragma unroll
            for (int d = 0; d < 4; d++) {
                float xs = sX[(m0 + d) * II + k];     // warp broadcast
                fma4(ar[d],  xs, wr);
                fma4(az[d],  xs, wz);
                fma4(ain[d], xs, wn);
            }
        }

        // ---- gates (registers) ----
        float4 hnew[4];
        #pragma unroll
        for (int d = 0; d < 4; d++) {
            float4 hold = ld4(sH + (m0 + d) * HH + c0);
            hnew[d].x = gru_gate(ar[d].x, az[d].x, ain[d].x, ahn[d].x, hold.x);
            hnew[d].y = gru_gate(ar[d].y, az[d].y, ain[d].y, ahn[d].y, hold.y);
            hnew[d].z = gru_gate(ar[d].z, az[d].z, ain[d].z, ahn[d].z, hold.z);
            hnew[d].w = gru_gate(ar[d].w, az[d].w, ain[d].w, ahn[d].w, hold.w);
        }
        __syncthreads();                  // all reads of old h complete
        #pragma unroll
        for (int d = 0; d < 4; d++)
            *(float4*)(sH + (m0 + d) * HH + c0) = hnew[d];
        __syncthreads();                  // new h visible

        // ---- y = h @ W_out^T + b_out ; feed back as next x ----
        float a0 = by, a1 = by, a2 = by, a3 = by;
        #pragma unroll 4
        for (int c = 0; c < HH; c++) {
            float wv = __ldg(g_WoutT + c * II + lane);   // 128B coalesced per warp
            a0 = fmaf(sH[(m0 + 0) * HH + c], wv, a0);
            a1 = fmaf(sH[(m0 + 1) * HH + c], wv, a1);
            a2 = fmaf(sH[(m0 + 2) * HH + c], wv, a2);
            a3 = fmaf(sH[(m0 + 3) * HH + c], wv, a3);
        }
        {
            size_t ob = (size_t)(rowBase + m0) * (STEPS * II) + (size_t)t * II + lane;
            out[ob + 0 * STEPS * II] = a0;
            out[ob + 1 * STEPS * II] = a1;
            out[ob + 2 * STEPS * II] = a2;
            out[ob + 3 * STEPS * II] = a3;
            sX[(m0 + 0) * II + lane] = a0;
            sX[(m0 + 1) * II + lane] = a1;
            sX[(m0 + 2) * II + lane] = a2;
            sX[(m0 + 3) * II + lane] = a3;
        }
        __syncthreads();                  // sX stable before next step's gi reads
    }
}

extern "C" void kernel_launch(void* const* d_in, const int* in_sizes, int n_in,
                              void* d_out, int out_size) {
    const float* x    = (const float*)d_in[0];
    const float* h    = (const float*)d_in[1];
    const float* Wih  = (const float*)d_in[2];
    const float* Whh  = (const float*)d_in[3];
    const float* bih  = (const float*)d_in[4];
    const float* bhh  = (const float*)d_in[5];
    const float* Wout = (const float*)d_in[6];
    const float* bout = (const float*)d_in[7];
    float* out = (float*)d_out;

    cudaFuncSetAttribute(gru_kernel, cudaFuncAttributeMaxDynamicSharedMemorySize, SMEM_BYTES);

    prep_kernel<<<192, 256>>>(Wih, Whh, Wout);
    gru_kernel<<<NCTA, NTHR, SMEM_BYTES>>>(x, h, bih, bhh, bout, out);
}

// round 5
// speedup vs baseline: 1.3347x; 1.3347x over previous
#include <cuda_runtime.h>
#include <cuda_bf16.h>

// B=16384, T=60, I=32, H=128, SEQLEN=30 -> 30 autoregressive steps (x_{t+1}=y_t).
// Only x[:,30,:] is consumed from the input.

#define BATCH   16384
#define TT      60
#define II      32
#define HH      128
#define STEPS   30
#define TM      32
#define NCTA    (BATCH / TM)   // 512
#define NTHR    256

typedef unsigned long long u64;

// ---- device scratch (transposed / repacked weights) ----
__device__ float g_WhhT[HH * 3 * HH];            // [k=128][j=384]; j in [256,384) = n-gate (streamed from L1)
__device__ float g_WihT[II * 3 * HH];            // [k=32][j=384]
__device__ __align__(16) float g_WoutP[HH * II]; // pair layout: [(c/2)*32 + lane] -> {W[lane][c], W[lane][c+1]}

__global__ void prep_kernel(const float* __restrict__ Wih,
                            const float* __restrict__ Whh,
                            const float* __restrict__ Wout) {
    int i = blockIdx.x * blockDim.x + threadIdx.x;
    if (i < 3 * HH * HH) {          // W_hh: (384,128) -> T[k][j]
        int j = i / HH, k = i % HH;
        g_WhhT[k * (3 * HH) + j] = Whh[i];
    }
    if (i < 3 * HH * II) {          // W_ih: (384,32) -> T[k][j]
        int j = i / II, k = i % II;
        g_WihT[k * (3 * HH) + j] = Wih[i];
    }
    if (i < (HH / 2) * II) {        // W_out: (32,128) -> pair-packed [c2][lane]
        int c2 = i >> 5, lane = i & 31;
        g_WoutP[i * 2 + 0] = Wout[lane * HH + 2 * c2 + 0];
        g_WoutP[i * 2 + 1] = Wout[lane * HH + 2 * c2 + 1];
    }
}

// smem: W_hh r/z gates [128][256] + W_ihT [32][384] + h [32][128] + x [32][32]
#define SM_WRZ_F (HH * 2 * HH)      // 32768 floats
#define SM_WIH_F (II * 3 * HH)      // 12288
#define SM_H_F   (TM * HH)          // 4096
#define SM_X_F   (TM * II)          // 1024
#define SMEM_BYTES ((SM_WRZ_F + SM_WIH_F + SM_H_F + SM_X_F) * 4)  // 200704 B

__device__ __forceinline__ float4 ld4(const float* p) { return *(const float4*)p; }
__device__ __forceinline__ float4 add4(float4 a, float4 b) {
    return make_float4(a.x + b.x, a.y + b.y, a.z + b.z, a.w + b.w);
}
__device__ __forceinline__ u64 pack2(float lo, float hi) {
    u64 r;
    asm("mov.b64 %0, {%1, %2};" : "=l"(r) : "r"(__float_as_uint(lo)), "r"(__float_as_uint(hi)));
    return r;
}
__device__ __forceinline__ float2 unpack2(u64 v) {
    unsigned lo, hi;
    asm("mov.b64 {%0, %1}, %2;" : "=r"(lo), "=r"(hi) : "l"(v));
    return make_float2(__uint_as_float(lo), __uint_as_float(hi));
}
__device__ __forceinline__ void fma2(u64& d, u64 a, u64 b) {
    asm("fma.rn.f32x2 %0, %1, %2, %0;" : "+l"(d) : "l"(a), "l"(b));
}

__device__ __forceinline__ float sigmoidf_fast(float v) {
    float e = __expf(-v);
    return __fdividef(1.0f, 1.0f + e);
}
__device__ __forceinline__ float tanhf_fast(float a) {
    float e2 = __expf(2.0f * a);
    return 1.0f - __fdividef(2.0f, e2 + 1.0f);
}
__device__ __forceinline__ float gru_gate(float rp, float zp, float inp, float hnp, float hold) {
    float r = sigmoidf_fast(rp);
    float z = sigmoidf_fast(zp);
    float n = tanhf_fast(fmaf(r, hnp, inp));
    return fmaf(z, hold - n, n);          // (1-z)*n + z*h
}

__global__ __launch_bounds__(NTHR, 1)
void gru_kernel(const float* __restrict__ x,
                const float* __restrict__ h0,
                const float* __restrict__ b_ih,
                const float* __restrict__ b_hh,
                const float* __restrict__ b_out,
                float* __restrict__ out) {
    extern __shared__ float sm[];
    float* sWrz = sm;                       // [128][256]  (r,z gate weights)
    float* sWih = sm + SM_WRZ_F;            // [32][384]
    float* sH   = sWih + SM_WIH_F;          // [32][128]
    float* sX   = sH + SM_H_F;              // [32][32]

    const int tid = threadIdx.x;
    const int rowBase = blockIdx.x * TM;

    // ---- stage into smem ----
    {   // r/z slice of W_hhT: row k keeps first 256 of 384 floats
        float4* dst = (float4*)sWrz;
        const float4* src = (const float4*)g_WhhT;
        #pragma unroll 4
        for (int i = tid; i < SM_WRZ_F / 4; i += NTHR) {
            int k = i >> 6, jj = i & 63;            // 64 float4 per row kept
            dst[i] = src[k * 96 + jj];              // 96 float4 per source row
        }
    }
    {
        float4* dst = (float4*)sWih;
        const float4* src = (const float4*)g_WihT;
        #pragma unroll 4
        for (int i = tid; i < SM_WIH_F / 4; i += NTHR) dst[i] = src[i];
    }
    {
        const float4* src = (const float4*)(h0 + (size_t)rowBase * HH);
        float4* dst = (float4*)sH;
        for (int i = tid; i < SM_H_F / 4; i += NTHR) dst[i] = src[i];
    }
    {   // x0 = x[:, 30, :]
        const float4* xv = (const float4*)x;
        float4* dst = (float4*)sX;
        int r = tid >> 3, q = tid & 7;
        dst[tid] = xv[(size_t)(rowBase + r) * (TT * II / 4) + (960 / 4) + q];
    }

    const int cm = tid >> 5, lane = tid & 31;
    const int m0 = cm * 4, c0 = lane * 4;

    // bias packs (constant across steps)
    const float4 brf  = add4(ld4(b_ih + c0),      ld4(b_hh + c0));
    const float4 bzf  = add4(ld4(b_ih + HH + c0), ld4(b_hh + HH + c0));
    const float4 binf = ld4(b_ih + 2 * HH + c0);
    const float4 bhnf = ld4(b_hh + 2 * HH + c0);
    const u64 br0 = pack2(brf.x, brf.y),   br1 = pack2(brf.z, brf.w);
    const u64 bz0 = pack2(bzf.x, bzf.y),   bz1 = pack2(bzf.z, bzf.w);
    const u64 bi0 = pack2(binf.x, binf.y), bi1 = pack2(binf.z, binf.w);
    const u64 bn0 = pack2(bhnf.x, bhnf.y), bn1 = pack2(bhnf.z, bhnf.w);
    const float by = b_out[lane];

    __syncthreads();   // staging visible; afterwards sH/sX rows are warp-private

    for (int t = 0; t < STEPS; t++) {
        u64 aR[4][2], aZ[4][2], aN[4][2], aI[4][2];
        #pragma unroll
        for (int d = 0; d < 4; d++) {
            aR[d][0] = br0; aR[d][1] = br1;
            aZ[d][0] = bz0; aZ[d][1] = bz1;
            aN[d][0] = bn0; aN[d][1] = bn1;
            aI[d][0] = bi0; aI[d][1] = bi1;
        }

        // ---- gh: K=128; r/z from smem, n-gate streamed from L1-resident global ----
        for (int k = 0; k < HH; k += 2) {
            const float* w0 = sWrz + k * 256;
            ulonglong2 wr0 = *(const ulonglong2*)(w0 + c0);
            ulonglong2 wz0 = *(const ulonglong2*)(w0 + HH + c0);
            ulonglong2 wr1 = *(const ulonglong2*)(w0 + 256 + c0);
            ulonglong2 wz1 = *(const ulonglong2*)(w0 + 256 + HH + c0);
            ulonglong2 wn0 = __ldg((const ulonglong2*)(g_WhhT + k * 384 + 256 + c0));
            ulonglong2 wn1 = __ldg((const ulonglong2*)(g_WhhT + (k + 1) * 384 + 256 + c0));
            #pragma unroll
            for (int d = 0; d < 4; d++) {
                float2 hv = *(const float2*)(sH + (m0 + d) * HH + k);   // warp broadcast
                u64 ha = pack2(hv.x, hv.x);
                u64 hb = pack2(hv.y, hv.y);
                fma2(aR[d][0], ha, wr0.x); fma2(aR[d][1], ha, wr0.y);
                fma2(aZ[d][0], ha, wz0.x); fma2(aZ[d][1], ha, wz0.y);
                fma2(aN[d][0], ha, wn0.x); fma2(aN[d][1], ha, wn0.y);
                fma2(aR[d][0], hb, wr1.x); fma2(aR[d][1], hb, wr1.y);
                fma2(aZ[d][0], hb, wz1.x); fma2(aZ[d][1], hb, wz1.y);
                fma2(aN[d][0], hb, wn1.x); fma2(aN[d][1], hb, wn1.y);
            }
        }

        // ---- gi: K=32 from smem ----
        for (int k = 0; k < II; k += 2) {
            const float* w0 = sWih + k * 384;
            ulonglong2 wr0 = *(const ulonglong2*)(w0 + c0);
            ulonglong2 wz0 = *(const ulonglong2*)(w0 + HH + c0);
            ulonglong2 wn0 = *(const ulonglong2*)(w0 + 2 * HH + c0);
            ulonglong2 wr1 = *(const ulonglong2*)(w0 + 384 + c0);
            ulonglong2 wz1 = *(const ulonglong2*)(w0 + 384 + HH + c0);
            ulonglong2 wn1 = *(const ulonglong2*)(w0 + 384 + 2 * HH + c0);
            #pragma unroll
            for (int d = 0; d < 4; d++) {
                float2 xv = *(const float2*)(sX + (m0 + d) * II + k);   // warp broadcast
                u64 xa = pack2(xv.x, xv.x);
                u64 xb = pack2(xv.y, xv.y);
                fma2(aR[d][0], xa, wr0.x); fma2(aR[d][1], xa, wr0.y);
                fma2(aZ[d][0], xa, wz0.x); fma2(aZ[d][1], xa, wz0.y);
                fma2(aI[d][0], xa, wn0.x); fma2(aI[d][1], xa, wn0.y);
                fma2(aR[d][0], xb, wr1.x); fma2(aR[d][1], xb, wr1.y);
                fma2(aZ[d][0], xb, wz1.x); fma2(aZ[d][1], xb, wz1.y);
                fma2(aI[d][0], xb, wn1.x); fma2(aI[d][1], xb, wn1.y);
            }
        }

        // ---- gates ----
        float4 hnew[4];
        #pragma unroll
        for (int d = 0; d < 4; d++) {
            float4 hold = ld4(sH + (m0 + d) * HH + c0);
            float2 rA = unpack2(aR[d][0]), rB = unpack2(aR[d][1]);
            float2 zA = unpack2(aZ[d][0]), zB = unpack2(aZ[d][1]);
            float2 iA = unpack2(aI[d][0]), iB = unpack2(aI[d][1]);
            float2 nA = unpack2(aN[d][0]), nB = unpack2(aN[d][1]);
            hnew[d].x = gru_gate(rA.x, zA.x, iA.x, nA.x, hold.x);
            hnew[d].y = gru_gate(rA.y, zA.y, iA.y, nA.y, hold.y);
            hnew[d].z = gru_gate(rB.x, zB.x, iB.x, nB.x, hold.z);
            hnew[d].w = gru_gate(rB.y, zB.y, iB.y, nB.y, hold.w);
        }
        __syncwarp();                       // all lanes done reading old sH rows
        #pragma unroll
        for (int d = 0; d < 4; d++)
            *(float4*)(sH + (m0 + d) * HH + c0) = hnew[d];
        __syncwarp();                       // new h visible within warp

        // ---- y = h @ W_out^T + b_out (f32x2 pairs over c) ----
        u64 yac[4] = {0ull, 0ull, 0ull, 0ull};
        const u64* wp_base = (const u64*)g_WoutP;
        #pragma unroll 4
        for (int c2 = 0; c2 < HH / 2; c2++) {
            u64 wp = __ldg(wp_base + c2 * 32 + lane);
            #pragma unroll
            for (int d = 0; d < 4; d++) {
                u64 hp = *(const u64*)(sH + (m0 + d) * HH + 2 * c2);    // warp broadcast
                fma2(yac[d], hp, wp);
            }
        }
        {
            size_t ob = (size_t)(rowBase + m0) * (STEPS * II) + (size_t)t * II + lane;
            #pragma unroll
            for (int d = 0; d < 4; d++) {
                float2 f = unpack2(yac[d]);
                float y = f.x + f.y + by;
                out[ob + (size_t)d * (STEPS * II)] = y;
                sX[(m0 + d) * II + lane] = y;
            }
        }
        __syncwarp();                       // sX stable before next step
    }
}

extern "C" void kernel_launch(void* const* d_in, const int* in_sizes, int n_in,
                              void* d_out, int out_size) {
    const float* x    = (const float*)d_in[0];
    const float* h    = (const float*)d_in[1];
    const float* Wih  = (const float*)d_in[2];
    const float* Whh  = (const float*)d_in[3];
    const float* bih  = (const float*)d_in[4];
    const float* bhh  = (const float*)d_in[5];
    const float* Wout = (const float*)d_in[6];
    const float* bout = (const float*)d_in[7];
    float* out = (float*)d_out;

    cudaFuncSetAttribute(gru_kernel, cudaFuncAttributeMaxDynamicSharedMemorySize, SMEM_BYTES);

    prep_kernel<<<192, 256>>>(Wih, Whh, Wout);
    gru_kernel<<<NCTA, NTHR, SMEM_BYTES>>>(x, h, bih, bhh, bout, out);
}